// round 12
// baseline (speedup 1.0000x reference)
#include <cuda_runtime.h>
#include <cuda_bf16.h>
#include <cstdint>

#define NROWS 32768
#define CCLS  2048
#define DDIM  512

// ---- tensor-path tiling (round-7/11 proven config) ----
#define BM 128
#define BN 128
#define BK 64                    // bf16 elems per chunk (128B per row)
#define KCHUNKS 24               // 3 products x (512/64)
#define TILE_BYTES 16384         // 128 rows x 128B
#define STAGE_BYTES (2 * TILE_BYTES)
#define NSTAGES 3
#define SMEM_TOTAL  (NSTAGES * STAGE_BYTES)   // 98304

#define NRB   (NROWS / BM)       // 256 rowblocks
#define NCT   (CCLS / BN)        // 16 col tiles (some dead)
#define LAG   32                 // softmax trails gemm by LAG rowblocks
#define GRP   (NCT + BM)         // 144 blocks per group: 16 gemm + 128 softmax
#define NGRP  (NRB + LAG)        // 288 groups
#define NEGHUGE -3.0e38f

// ---- scratch (__device__ globals; no cudaMalloc allowed) ----
__device__ __nv_bfloat16 g_Ah[(size_t)NROWS * DDIM];
__device__ __nv_bfloat16 g_Al[(size_t)NROWS * DDIM];
__device__ __nv_bfloat16 g_Bh[(size_t)CCLS * DDIM];   // compacted (visited only)
__device__ __nv_bfloat16 g_Bl[(size_t)CCLS * DDIM];   // compacted
__device__ float g_m2c[CCLS];                          // compacted ||mu||^2
__device__ int   g_pos[CCLS];                          // class -> compacted slot
__device__ int   g_V;                                  // number of visited classes
__device__ int   g_cnt[NRB];                           // per-rowblock completion count

// ===========================================================================
// PTX helpers (all supported on plain sm_103 target)
// ===========================================================================
__device__ __forceinline__ uint32_t smem_u32(const void* p) {
    uint32_t a;
    asm("{ .reg .u64 t; cvta.to.shared.u64 t, %1; cvt.u32.u64 %0, t; }" : "=r"(a) : "l"(p));
    return a;
}

__device__ __forceinline__ void cp16(uint32_t dst, const void* src) {
    asm volatile("cp.async.cg.shared.global.L2::128B [%0], [%1], 16;" :: "r"(dst), "l"(src));
}
#define CP_COMMIT() asm volatile("cp.async.commit_group;" ::: "memory")
#define CP_WAIT1()  asm volatile("cp.async.wait_group 1;" ::: "memory")

__device__ __forceinline__ void ldsm4(uint32_t* r, uint32_t addr) {
    asm volatile("ldmatrix.sync.aligned.m8n8.x4.shared.b16 {%0,%1,%2,%3}, [%4];"
                 : "=r"(r[0]), "=r"(r[1]), "=r"(r[2]), "=r"(r[3]) : "r"(addr));
}

__device__ __forceinline__ void mma16816(float* d, const uint32_t* a, const uint32_t* b) {
    asm volatile("mma.sync.aligned.m16n8k16.row.col.f32.bf16.bf16.f32 "
                 "{%0,%1,%2,%3}, {%4,%5,%6,%7}, {%8,%9}, {%0,%1,%2,%3};"
                 : "+f"(d[0]), "+f"(d[1]), "+f"(d[2]), "+f"(d[3])
                 : "r"(a[0]), "r"(a[1]), "r"(a[2]), "r"(a[3]), "r"(b[0]), "r"(b[1]));
}

// ===========================================================================
// Kernel: prefix scan over visited flags -> pos / V; zero completion counters
// ===========================================================================
__global__ __launch_bounds__(1024) void k_scan(const float* __restrict__ cK) {
    __shared__ int s[1024];
    const int t = threadIdx.x;
    if (t < NRB) g_cnt[t] = 0;               // re-zero every launch (graph replay)
    const int f0 = (cK[2 * t]     != 0.f) ? 1 : 0;
    const int f1 = (cK[2 * t + 1] != 0.f) ? 1 : 0;
    const int p = f0 + f1;
    int v = p;
    s[t] = v;
    __syncthreads();
    #pragma unroll
    for (int off = 1; off < 1024; off <<= 1) {
        int add = (t >= off) ? s[t - off] : 0;
        __syncthreads();
        v += add;
        s[t] = v;
        __syncthreads();
    }
    const int excl = v - p;                  // exclusive prefix (pairs)
    g_pos[2 * t]     = excl;
    g_pos[2 * t + 1] = excl + f0;
    if (t == 1023) g_V = v;
}

// ===========================================================================
// Kernel: convert X -> bf16 hi/lo
// ===========================================================================
__global__ __launch_bounds__(256) void k_convX(const float* __restrict__ X) {
    const int idx = blockIdx.x * 256 + threadIdx.x;        // float4 index
    float4 v = ((const float4*)X)[idx];
    __nv_bfloat16 h0 = __float2bfloat16(v.x), h1 = __float2bfloat16(v.y);
    __nv_bfloat16 h2 = __float2bfloat16(v.z), h3 = __float2bfloat16(v.w);
    __nv_bfloat16 l0 = __float2bfloat16(v.x - __bfloat162float(h0));
    __nv_bfloat16 l1 = __float2bfloat16(v.y - __bfloat162float(h1));
    __nv_bfloat16 l2 = __float2bfloat16(v.z - __bfloat162float(h2));
    __nv_bfloat16 l3 = __float2bfloat16(v.w - __bfloat162float(h3));
    __nv_bfloat162* Ah = (__nv_bfloat162*)g_Ah;
    __nv_bfloat162* Al = (__nv_bfloat162*)g_Al;
    __nv_bfloat162 p;
    p.x = h0; p.y = h1; Ah[idx * 2]     = p;
    p.x = h2; p.y = h3; Ah[idx * 2 + 1] = p;
    p.x = l0; p.y = l1; Al[idx * 2]     = p;
    p.x = l2; p.y = l3; Al[idx * 2 + 1] = p;
}

// ===========================================================================
// Kernel: convert visited MU rows -> compacted bf16 hi/lo + m2
// ===========================================================================
__global__ __launch_bounds__(128) void k_convMU(const float* __restrict__ MU,
                                                const float* __restrict__ cK) {
    const int c = blockIdx.x;
    if (cK[c] == 0.f) return;                 // unvisited: skip entirely
    const int p = g_pos[c];
    const size_t src = (size_t)c * DDIM;
    const size_t dst = (size_t)p * DDIM;
    float s = 0.f;
    #pragma unroll
    for (int j = 0; j < 4; j++) {
        int d = threadIdx.x + j * 128;
        float x = MU[src + d];
        __nv_bfloat16 h = __float2bfloat16(x);
        __nv_bfloat16 l = __float2bfloat16(x - __bfloat162float(h));
        g_Bh[dst + d] = h;
        g_Bl[dst + d] = l;
        s = fmaf(x, x, s);
    }
    #pragma unroll
    for (int o = 16; o; o >>= 1) s += __shfl_xor_sync(0xffffffffu, s, o);
    __shared__ float sm[4];
    if ((threadIdx.x & 31) == 0) sm[threadIdx.x >> 5] = s;
    __syncthreads();
    if (threadIdx.x == 0) g_m2c[p] = sm[0] + sm[1] + sm[2] + sm[3];
}

// ===========================================================================
// Fused GEMM + softmax kernel (1-D grid of groups).
//   group g, slot r<16  : gemm tile (rowblock g, col tile r)       [g < NRB]
//   group g, slot r>=16 : softmax row (g-LAG)*128 + (r-16)         [g >= LAG]
// GEMM CTAs bump g_cnt[rb] when their tile of S is globally visible;
// softmax CTAs spin until all active col tiles of their rowblock landed.
// ===========================================================================
__device__ __forceinline__ void load_chunk(uint32_t stb, int t,
                                           int bm, int bn, int tid) {
    const int phase = t >> 3;
    const int koff  = (t & 7) * BK;
    const __nv_bfloat16* A = (phase == 1) ? g_Al : g_Ah;
    const __nv_bfloat16* B = (phase == 2) ? g_Bl : g_Bh;
    const uint32_t bs = stb + TILE_BYTES;
    #pragma unroll
    for (int i = 0; i < 4; i++) {
        int q = tid + i * 256;
        int r = q >> 3, c = q & 7;
        uint32_t off = r * 128 + ((c * 16) ^ ((r & 7) << 4));
        cp16(stb + off, A + (size_t)(bm + r) * DDIM + koff + c * 8);
    }
    #pragma unroll
    for (int i = 0; i < 4; i++) {
        int q = tid + i * 256;
        int r = q >> 3, c = q & 7;
        uint32_t off = r * 128 + ((c * 16) ^ ((r & 7) << 4));
        cp16(bs + off, B + (size_t)(bn + r) * DDIM + koff + c * 8);
    }
}

__device__ __forceinline__ float block_red(float v, int mode, float* sred, int tid) {
    #pragma unroll
    for (int o = 16; o; o >>= 1) {
        float t = __shfl_xor_sync(0xffffffffu, v, o);
        v = (mode == 1) ? fmaxf(v, t) : (v + t);
    }
    __syncthreads();
    if ((tid & 31) == 0) sred[tid >> 5] = v;
    __syncthreads();
    float r;
    if (mode == 1) {
        r = fmaxf(fmaxf(fmaxf(sred[0], sred[1]), fmaxf(sred[2], sred[3])),
                  fmaxf(fmaxf(sred[4], sred[5]), fmaxf(sred[6], sred[7])));
    } else {
        r = ((sred[0] + sred[1]) + (sred[2] + sred[3])) +
            ((sred[4] + sred[5]) + (sred[6] + sred[7]));
    }
    return r;
}

__global__ __launch_bounds__(256, 2) void k_fused(float* __restrict__ S,
                                                  const float* __restrict__ cK) {
    extern __shared__ char smem[];
    __shared__ float sred[8];
    const int b = blockIdx.x;
    const int g = b / GRP;
    const int r = b - g * GRP;
    const int tid = threadIdx.x;

    if (r < NCT) {
        // ===================== GEMM tile ==================================
        if (g >= NRB) return;                 // trailing groups: no gemm part
        const int V = g_V;
        const int bn = r * BN;
        if (bn >= V) return;                  // dead col tile (no increment)
        const int bm = g * BM;

        const uint32_t sb = smem_u32(smem);
        const int wid = tid >> 5, l = tid & 31;
        const int wm = (wid & 1) * 64;
        const int wn = (wid >> 1) * 32;

        float acc[4][4][4];
        #pragma unroll
        for (int i = 0; i < 4; i++)
            #pragma unroll
            for (int j = 0; j < 4; j++)
                #pragma unroll
                for (int k = 0; k < 4; k++) acc[i][j][k] = 0.f;

        const uint32_t sw   = (uint32_t)(l & 7) << 4;
        const int rowA = wm + (l & 15);
        const uint32_t aColSel = ((uint32_t)(l >> 4)) << 4;
        const int rowB = wn + ((l >> 4) << 3) + (l & 7);
        const uint32_t bColSel = ((uint32_t)((l >> 3) & 1)) << 4;

        load_chunk(sb + 0 * STAGE_BYTES, 0, bm, bn, tid); CP_COMMIT();
        load_chunk(sb + 1 * STAGE_BYTES, 1, bm, bn, tid); CP_COMMIT();

        int rs = 0, ws = 2;
        for (int t = 0; t < KCHUNKS; t++) {
            CP_WAIT1();
            __syncthreads();

            if (t + 2 < KCHUNKS) load_chunk(sb + ws * STAGE_BYTES, t + 2, bm, bn, tid);
            CP_COMMIT();

            const uint32_t as = sb + rs * STAGE_BYTES;
            const uint32_t bs = as + TILE_BYTES;

            #pragma unroll
            for (int ks = 0; ks < 4; ks++) {
                const uint32_t kb = (uint32_t)ks * 32;
                uint32_t a[4][4], bfr[2][4];
                #pragma unroll
                for (int bt = 0; bt < 2; bt++)
                    ldsm4(bfr[bt], bs + (uint32_t)(rowB + bt * 16) * 128 + ((kb + bColSel) ^ sw));
                #pragma unroll
                for (int mt = 0; mt < 4; mt++)
                    ldsm4(a[mt], as + (uint32_t)(rowA + mt * 16) * 128 + ((kb + aColSel) ^ sw));
                #pragma unroll
                for (int mt = 0; mt < 4; mt++) {
                    mma16816(acc[mt][0], a[mt], &bfr[0][0]);
                    mma16816(acc[mt][1], a[mt], &bfr[0][2]);
                    mma16816(acc[mt][2], a[mt], &bfr[1][0]);
                    mma16816(acc[mt][3], a[mt], &bfr[1][2]);
                }
            }

            rs = (rs == 2) ? 0 : rs + 1;
            ws = (ws == 2) ? 0 : ws + 1;
        }

        // epilogue: coalesced stores at COMPACTED columns, guard c < V
        const int ccomp = bn + wn + (l & 3) * 2;
        const int rbase = bm + wm + (l >> 2);
        float m2v[4][2];
        bool  ok0[4], ok1[4];
        #pragma unroll
        for (int nt = 0; nt < 4; nt++) {
            const int c0 = ccomp + nt * 8;
            ok0[nt] = (c0 < V); ok1[nt] = (c0 + 1 < V);
            m2v[nt][0] = ok0[nt] ? g_m2c[c0]     : 0.f;
            m2v[nt][1] = ok1[nt] ? g_m2c[c0 + 1] : 0.f;
        }
        #pragma unroll
        for (int mt = 0; mt < 4; mt++) {
            const int r0 = rbase + mt * 16;
            const int r1 = r0 + 8;
            #pragma unroll
            for (int nt = 0; nt < 4; nt++) {
                const int c0 = ccomp + nt * 8;
                if (ok1[nt]) {
                    float2 v0, v1;
                    v0.x = 2.f * acc[mt][nt][0] - m2v[nt][0];
                    v0.y = 2.f * acc[mt][nt][1] - m2v[nt][1];
                    v1.x = 2.f * acc[mt][nt][2] - m2v[nt][0];
                    v1.y = 2.f * acc[mt][nt][3] - m2v[nt][1];
                    *(float2*)(S + (size_t)r0 * CCLS + c0) = v0;
                    *(float2*)(S + (size_t)r1 * CCLS + c0) = v1;
                } else if (ok0[nt]) {
                    S[(size_t)r0 * CCLS + c0] = 2.f * acc[mt][nt][0] - m2v[nt][0];
                    S[(size_t)r1 * CCLS + c0] = 2.f * acc[mt][nt][2] - m2v[nt][0];
                }
            }
        }

        // publish: all threads' stores -> fence -> bar -> single increment
        __threadfence();
        __syncthreads();
        if (tid == 0) atomicAdd(&g_cnt[g], 1);
    } else {
        // ===================== softmax row ================================
        if (g < LAG) return;                  // leading groups: no softmax part
        const int row = (g - LAG) * BM + (r - NCT);
        const int rb = row >> 7;
        const int V = g_V;
        const int nact = (V + BN - 1) / BN;

        if (tid == 0) {
            while (atomicAdd(&g_cnt[rb], 0) < nact) __nanosleep(200);
        }
        __syncthreads();
        __threadfence();

        float* sm_e = (float*)smem;           // 8 KB staging in dynamic smem
        float4* sp = (float4*)(S + (size_t)row * CCLS);

        float4 v0 = sp[tid];
        float4 v1 = sp[tid + 256];
        const int p0 = tid * 4;
        const int p1 = 1024 + tid * 4;
        if (p0 + 0 >= V) v0.x = NEGHUGE;
        if (p0 + 1 >= V) v0.y = NEGHUGE;
        if (p0 + 2 >= V) v0.z = NEGHUGE;
        if (p0 + 3 >= V) v0.w = NEGHUGE;
        if (p1 + 0 >= V) v1.x = NEGHUGE;
        if (p1 + 1 >= V) v1.y = NEGHUGE;
        if (p1 + 2 >= V) v1.z = NEGHUGE;
        if (p1 + 3 >= V) v1.w = NEGHUGE;

        float mx = fmaxf(fmaxf(fmaxf(v0.x, v0.y), fmaxf(v0.z, v0.w)),
                         fmaxf(fmaxf(v1.x, v1.y), fmaxf(v1.z, v1.w)));
        mx = block_red(mx, 1, sred, tid);

        float4 e0, e1;
        e0.x = __expf(v0.x - mx); e0.y = __expf(v0.y - mx);
        e0.z = __expf(v0.z - mx); e0.w = __expf(v0.w - mx);
        e1.x = __expf(v1.x - mx); e1.y = __expf(v1.y - mx);
        e1.z = __expf(v1.z - mx); e1.w = __expf(v1.w - mx);
        float sum = ((e0.x + e0.y) + (e0.z + e0.w)) + ((e1.x + e1.y) + (e1.z + e1.w));
        sum = block_red(sum, 2, sred, tid);
        const float inv = 1.f / sum;

        ((float4*)sm_e)[tid]       = make_float4(e0.x * inv, e0.y * inv, e0.z * inv, e0.w * inv);
        ((float4*)sm_e)[tid + 256] = make_float4(e1.x * inv, e1.y * inv, e1.z * inv, e1.w * inv);
        __syncthreads();

        const float4* cp = (const float4*)cK;
        const int4*   qp = (const int4*)g_pos;
        float4 c0 = cp[tid], c1 = cp[tid + 256];
        int4   q0 = qp[tid], q1 = qp[tid + 256];
        float4 o0, o1;
        o0.x = (c0.x == 0.f) ? 0.f : sm_e[q0.x];
        o0.y = (c0.y == 0.f) ? 0.f : sm_e[q0.y];
        o0.z = (c0.z == 0.f) ? 0.f : sm_e[q0.z];
        o0.w = (c0.w == 0.f) ? 0.f : sm_e[q0.w];
        o1.x = (c1.x == 0.f) ? 0.f : sm_e[q1.x];
        o1.y = (c1.y == 0.f) ? 0.f : sm_e[q1.y];
        o1.z = (c1.z == 0.f) ? 0.f : sm_e[q1.z];
        o1.w = (c1.w == 0.f) ? 0.f : sm_e[q1.w];
        sp[tid]       = o0;
        sp[tid + 256] = o1;
    }
}

// ===========================================================================
extern "C" void kernel_launch(void* const* d_in, const int* in_sizes, int n_in,
                              void* d_out, int out_size) {
    const float* X  = (const float*)d_in[0];   // (N, D) fp32
    const float* MU = (const float*)d_in[1];   // (C, D) fp32
    const float* cK = (const float*)d_in[2];   // (C,)   fp32
    float* out = (float*)d_out;                // (N, C) fp32

    cudaFuncSetAttribute(k_fused, cudaFuncAttributeMaxDynamicSharedMemorySize, SMEM_TOTAL);

    k_scan<<<1, 1024>>>(cK);
    k_convX<<<(NROWS * DDIM) / 4 / 256, 256>>>(X);
    k_convMU<<<CCLS, 128>>>(MU, cK);

    k_fused<<<NGRP * GRP, 256, SMEM_TOTAL>>>(out, cK);
}

// round 13
// speedup vs baseline: 1.0213x; 1.0213x over previous
#include <cuda_runtime.h>
#include <cuda_bf16.h>
#include <cstdint>

#define NROWS 32768
#define CCLS  2048
#define DDIM  512

// ---- tensor-path tiling (round-7/11 proven config) ----
#define BM 128
#define BN 128
#define BK 64                    // bf16 elems per chunk (128B per row)
#define KCHUNKS 24               // 3 products x (512/64)
#define TILE_BYTES 16384         // 128 rows x 128B
#define STAGE_BYTES (2 * TILE_BYTES)
#define NSTAGES 3
#define SMEM_TOTAL  (NSTAGES * STAGE_BYTES)   // 98304 (>= 64KB softmax staging)

#define NRB (NROWS / BM)         // 256 rowblocks
#define NEGHUGE -3.0e38f

// ---- scratch (__device__ globals; no cudaMalloc allowed) ----
__device__ __nv_bfloat16 g_Ah[(size_t)NROWS * DDIM];
__device__ __nv_bfloat16 g_Al[(size_t)NROWS * DDIM];
__device__ __nv_bfloat16 g_Bh[(size_t)CCLS * DDIM];   // compacted (visited only)
__device__ __nv_bfloat16 g_Bl[(size_t)CCLS * DDIM];   // compacted
__device__ float g_m2c[CCLS];                          // compacted ||mu||^2
__device__ int   g_pos[CCLS];                          // class -> compacted slot
__device__ int   g_V;                                  // number of visited classes
__device__ int   g_cnt[NRB];                           // per-rowblock tile counter

// ===========================================================================
// PTX helpers (all supported on plain sm_103 target)
// ===========================================================================
__device__ __forceinline__ uint32_t smem_u32(const void* p) {
    uint32_t a;
    asm("{ .reg .u64 t; cvta.to.shared.u64 t, %1; cvt.u32.u64 %0, t; }" : "=r"(a) : "l"(p));
    return a;
}

__device__ __forceinline__ void cp16(uint32_t dst, const void* src) {
    asm volatile("cp.async.cg.shared.global.L2::128B [%0], [%1], 16;" :: "r"(dst), "l"(src));
}
#define CP_COMMIT() asm volatile("cp.async.commit_group;" ::: "memory")
#define CP_WAIT1()  asm volatile("cp.async.wait_group 1;" ::: "memory")

__device__ __forceinline__ void ldsm4(uint32_t* r, uint32_t addr) {
    asm volatile("ldmatrix.sync.aligned.m8n8.x4.shared.b16 {%0,%1,%2,%3}, [%4];"
                 : "=r"(r[0]), "=r"(r[1]), "=r"(r[2]), "=r"(r[3]) : "r"(addr));
}

__device__ __forceinline__ void mma16816(float* d, const uint32_t* a, const uint32_t* b) {
    asm volatile("mma.sync.aligned.m16n8k16.row.col.f32.bf16.bf16.f32 "
                 "{%0,%1,%2,%3}, {%4,%5,%6,%7}, {%8,%9}, {%0,%1,%2,%3};"
                 : "+f"(d[0]), "+f"(d[1]), "+f"(d[2]), "+f"(d[3])
                 : "r"(a[0]), "r"(a[1]), "r"(a[2]), "r"(a[3]), "r"(b[0]), "r"(b[1]));
}

// ===========================================================================
// Kernel: prefix scan over visited flags -> pos / V; zero rowblock counters
// ===========================================================================
__global__ __launch_bounds__(1024) void k_scan(const float* __restrict__ cK) {
    __shared__ int s[1024];
    const int t = threadIdx.x;
    if (t < NRB) g_cnt[t] = 0;               // re-zero every launch (graph replay)
    const int f0 = (cK[2 * t]     != 0.f) ? 1 : 0;
    const int f1 = (cK[2 * t + 1] != 0.f) ? 1 : 0;
    const int p = f0 + f1;
    int v = p;
    s[t] = v;
    __syncthreads();
    #pragma unroll
    for (int off = 1; off < 1024; off <<= 1) {
        int add = (t >= off) ? s[t - off] : 0;
        __syncthreads();
        v += add;
        s[t] = v;
        __syncthreads();
    }
    const int excl = v - p;                  // exclusive prefix (pairs)
    g_pos[2 * t]     = excl;
    g_pos[2 * t + 1] = excl + f0;
    if (t == 1023) g_V = v;
}

// ===========================================================================
// Kernel: convert X -> bf16 hi/lo
// ===========================================================================
__global__ __launch_bounds__(256) void k_convX(const float* __restrict__ X) {
    const int idx = blockIdx.x * 256 + threadIdx.x;        // float4 index
    float4 v = ((const float4*)X)[idx];
    __nv_bfloat16 h0 = __float2bfloat16(v.x), h1 = __float2bfloat16(v.y);
    __nv_bfloat16 h2 = __float2bfloat16(v.z), h3 = __float2bfloat16(v.w);
    __nv_bfloat16 l0 = __float2bfloat16(v.x - __bfloat162float(h0));
    __nv_bfloat16 l1 = __float2bfloat16(v.y - __bfloat162float(h1));
    __nv_bfloat16 l2 = __float2bfloat16(v.z - __bfloat162float(h2));
    __nv_bfloat16 l3 = __float2bfloat16(v.w - __bfloat162float(h3));
    __nv_bfloat162* Ah = (__nv_bfloat162*)g_Ah;
    __nv_bfloat162* Al = (__nv_bfloat162*)g_Al;
    __nv_bfloat162 p;
    p.x = h0; p.y = h1; Ah[idx * 2]     = p;
    p.x = h2; p.y = h3; Ah[idx * 2 + 1] = p;
    p.x = l0; p.y = l1; Al[idx * 2]     = p;
    p.x = l2; p.y = l3; Al[idx * 2 + 1] = p;
}

// ===========================================================================
// Kernel: convert visited MU rows -> compacted bf16 hi/lo + m2
// ===========================================================================
__global__ __launch_bounds__(128) void k_convMU(const float* __restrict__ MU,
                                                const float* __restrict__ cK) {
    const int c = blockIdx.x;
    if (cK[c] == 0.f) return;                 // unvisited: skip entirely
    const int p = g_pos[c];
    const size_t src = (size_t)c * DDIM;
    const size_t dst = (size_t)p * DDIM;
    float s = 0.f;
    #pragma unroll
    for (int j = 0; j < 4; j++) {
        int d = threadIdx.x + j * 128;
        float x = MU[src + d];
        __nv_bfloat16 h = __float2bfloat16(x);
        __nv_bfloat16 l = __float2bfloat16(x - __bfloat162float(h));
        g_Bh[dst + d] = h;
        g_Bl[dst + d] = l;
        s = fmaf(x, x, s);
    }
    #pragma unroll
    for (int o = 16; o; o >>= 1) s += __shfl_xor_sync(0xffffffffu, s, o);
    __shared__ float sm[4];
    if ((threadIdx.x & 31) == 0) sm[threadIdx.x >> 5] = s;
    __syncthreads();
    if (threadIdx.x == 0) g_m2c[p] = sm[0] + sm[1] + sm[2] + sm[3];
}

// ===========================================================================
// GEMM over COMPACTED columns, compacted coalesced stores.
// The LAST CTA to finish a rowblock also performs that rowblock's softmax
// (warp-per-row, staged in the now-free pipeline smem). No CTA ever waits.
// ===========================================================================
__device__ __forceinline__ void load_chunk(uint32_t stb, int t,
                                           int bm, int bn, int tid) {
    const int phase = t >> 3;
    const int koff  = (t & 7) * BK;
    const __nv_bfloat16* A = (phase == 1) ? g_Al : g_Ah;
    const __nv_bfloat16* B = (phase == 2) ? g_Bl : g_Bh;
    const uint32_t bs = stb + TILE_BYTES;
    #pragma unroll
    for (int i = 0; i < 4; i++) {
        int q = tid + i * 256;
        int r = q >> 3, c = q & 7;
        uint32_t off = r * 128 + ((c * 16) ^ ((r & 7) << 4));
        cp16(stb + off, A + (size_t)(bm + r) * DDIM + koff + c * 8);
    }
    #pragma unroll
    for (int i = 0; i < 4; i++) {
        int q = tid + i * 256;
        int r = q >> 3, c = q & 7;
        uint32_t off = r * 128 + ((c * 16) ^ ((r & 7) << 4));
        cp16(bs + off, B + (size_t)(bn + r) * DDIM + koff + c * 8);
    }
}

__global__ __launch_bounds__(256, 2) void k_gemm_fused(float* __restrict__ S,
                                                       const float* __restrict__ cK) {
    const int V = g_V;
    const int bn = blockIdx.x * BN;
    if (bn >= V) return;                      // dead col tile (not counted)

    extern __shared__ char smem[];
    const uint32_t sb = smem_u32(smem);
    const int tid = threadIdx.x;
    const int wid = tid >> 5, l = tid & 31;
    const int rb = blockIdx.y;
    const int bm = rb * BM;
    const int wm = (wid & 1) * 64;
    const int wn = (wid >> 1) * 32;

    float acc[4][4][4];
    #pragma unroll
    for (int i = 0; i < 4; i++)
        #pragma unroll
        for (int j = 0; j < 4; j++)
            #pragma unroll
            for (int k = 0; k < 4; k++) acc[i][j][k] = 0.f;

    const uint32_t sw   = (uint32_t)(l & 7) << 4;
    const int rowA = wm + (l & 15);
    const uint32_t aColSel = ((uint32_t)(l >> 4)) << 4;
    const int rowB = wn + ((l >> 4) << 3) + (l & 7);
    const uint32_t bColSel = ((uint32_t)((l >> 3) & 1)) << 4;

    load_chunk(sb + 0 * STAGE_BYTES, 0, bm, bn, tid); CP_COMMIT();
    load_chunk(sb + 1 * STAGE_BYTES, 1, bm, bn, tid); CP_COMMIT();

    int rs = 0, ws = 2;
    for (int t = 0; t < KCHUNKS; t++) {
        CP_WAIT1();
        __syncthreads();

        if (t + 2 < KCHUNKS) load_chunk(sb + ws * STAGE_BYTES, t + 2, bm, bn, tid);
        CP_COMMIT();

        const uint32_t as = sb + rs * STAGE_BYTES;
        const uint32_t bs = as + TILE_BYTES;

        #pragma unroll
        for (int ks = 0; ks < 4; ks++) {
            const uint32_t kb = (uint32_t)ks * 32;
            uint32_t a[4][4], bfr[2][4];
            #pragma unroll
            for (int bt = 0; bt < 2; bt++)
                ldsm4(bfr[bt], bs + (uint32_t)(rowB + bt * 16) * 128 + ((kb + bColSel) ^ sw));
            #pragma unroll
            for (int mt = 0; mt < 4; mt++)
                ldsm4(a[mt], as + (uint32_t)(rowA + mt * 16) * 128 + ((kb + aColSel) ^ sw));
            #pragma unroll
            for (int mt = 0; mt < 4; mt++) {
                mma16816(acc[mt][0], a[mt], &bfr[0][0]);
                mma16816(acc[mt][1], a[mt], &bfr[0][2]);
                mma16816(acc[mt][2], a[mt], &bfr[1][0]);
                mma16816(acc[mt][3], a[mt], &bfr[1][2]);
            }
        }

        rs = (rs == 2) ? 0 : rs + 1;
        ws = (ws == 2) ? 0 : ws + 1;
    }

    // epilogue: coalesced stores at COMPACTED columns, guard c < V
    {
        const int ccomp = bn + wn + (l & 3) * 2;
        const int rbase = bm + wm + (l >> 2);
        float m2v[4][2];
        bool  ok0[4], ok1[4];
        #pragma unroll
        for (int nt = 0; nt < 4; nt++) {
            const int c0 = ccomp + nt * 8;
            ok0[nt] = (c0 < V); ok1[nt] = (c0 + 1 < V);
            m2v[nt][0] = ok0[nt] ? g_m2c[c0]     : 0.f;
            m2v[nt][1] = ok1[nt] ? g_m2c[c0 + 1] : 0.f;
        }
        #pragma unroll
        for (int mt = 0; mt < 4; mt++) {
            const int r0 = rbase + mt * 16;
            const int r1 = r0 + 8;
            #pragma unroll
            for (int nt = 0; nt < 4; nt++) {
                const int c0 = ccomp + nt * 8;
                if (ok1[nt]) {
                    float2 v0, v1;
                    v0.x = 2.f * acc[mt][nt][0] - m2v[nt][0];
                    v0.y = 2.f * acc[mt][nt][1] - m2v[nt][1];
                    v1.x = 2.f * acc[mt][nt][2] - m2v[nt][0];
                    v1.y = 2.f * acc[mt][nt][3] - m2v[nt][1];
                    *(float2*)(S + (size_t)r0 * CCLS + c0) = v0;
                    *(float2*)(S + (size_t)r1 * CCLS + c0) = v1;
                } else if (ok0[nt]) {
                    S[(size_t)r0 * CCLS + c0] = 2.f * acc[mt][nt][0] - m2v[nt][0];
                    S[(size_t)r1 * CCLS + c0] = 2.f * acc[mt][nt][2] - m2v[nt][0];
                }
            }
        }
    }

    // publish tile; detect last CTA of this rowblock
    __threadfence();
    __syncthreads();
    __shared__ int slast;
    const int nact = (V + BN - 1) / BN;
    if (tid == 0) slast = (atomicAdd(&g_cnt[rb], 1) == nact - 1) ? 1 : 0;
    __syncthreads();
    if (!slast) return;
    __threadfence();                          // see all other tiles' stores

    // ======== softmax for this rowblock: warp-per-row, 8KB staging/warp ====
    float* se = (float*)smem + wid * 2048;    // reuse pipeline smem (64KB of 96KB)
    const float4* cp4 = (const float4*)cK;
    const int4*   qp4 = (const int4*)g_pos;

    for (int rr = wid; rr < BM; rr += 8) {
        float4* srow = (float4*)(S + (size_t)(bm + rr) * CCLS);

        // pass A: load compacted scores, mask p>=V, stage raw, track max
        float mx = NEGHUGE;
        #pragma unroll
        for (int j = 0; j < 16; j++) {
            const int c4 = j * 32 + l;
            float4 v = srow[c4];
            const int p = c4 * 4;
            if (p + 0 >= V) v.x = NEGHUGE;
            if (p + 1 >= V) v.y = NEGHUGE;
            if (p + 2 >= V) v.z = NEGHUGE;
            if (p + 3 >= V) v.w = NEGHUGE;
            ((float4*)se)[c4] = v;
            mx = fmaxf(mx, fmaxf(fmaxf(v.x, v.y), fmaxf(v.z, v.w)));
        }
        #pragma unroll
        for (int o = 16; o; o >>= 1) mx = fmaxf(mx, __shfl_xor_sync(0xffffffffu, mx, o));

        // pass B: exp + sum, stage exp
        float sum = 0.f;
        #pragma unroll
        for (int j = 0; j < 16; j++) {
            const int c4 = j * 32 + l;
            float4 v = ((float4*)se)[c4];
            float4 e;
            e.x = __expf(v.x - mx); e.y = __expf(v.y - mx);
            e.z = __expf(v.z - mx); e.w = __expf(v.w - mx);
            ((float4*)se)[c4] = e;
            sum += (e.x + e.y) + (e.z + e.w);
        }
        #pragma unroll
        for (int o = 16; o; o >>= 1) sum += __shfl_xor_sync(0xffffffffu, sum, o);
        const float inv = 1.f / sum;
        __syncwarp();

        // pass C: gather-expand to full column space, coalesced stores
        #pragma unroll
        for (int j = 0; j < 16; j++) {
            const int c4 = j * 32 + l;
            const float4 ck = cp4[c4];
            const int4   q  = qp4[c4];
            float4 o;
            o.x = (ck.x == 0.f) ? 0.f : se[q.x] * inv;
            o.y = (ck.y == 0.f) ? 0.f : se[q.y] * inv;
            o.z = (ck.z == 0.f) ? 0.f : se[q.z] * inv;
            o.w = (ck.w == 0.f) ? 0.f : se[q.w] * inv;
            srow[c4] = o;
        }
        __syncwarp();
    }
}

// ===========================================================================
extern "C" void kernel_launch(void* const* d_in, const int* in_sizes, int n_in,
                              void* d_out, int out_size) {
    const float* X  = (const float*)d_in[0];   // (N, D) fp32
    const float* MU = (const float*)d_in[1];   // (C, D) fp32
    const float* cK = (const float*)d_in[2];   // (C,)   fp32
    float* out = (float*)d_out;                // (N, C) fp32

    cudaFuncSetAttribute(k_gemm_fused, cudaFuncAttributeMaxDynamicSharedMemorySize, SMEM_TOTAL);

    k_scan<<<1, 1024>>>(cK);
    k_convX<<<(NROWS * DDIM) / 4 / 256, 256>>>(X);
    k_convMU<<<CCLS, 128>>>(MU, cK);

    dim3 grid(CCLS / BN, NROWS / BM);          // (16, 256); dead tiles exit early
    k_gemm_fused<<<grid, 256, SMEM_TOTAL>>>(out, cK);
}

// round 14
// speedup vs baseline: 1.3831x; 1.3543x over previous
#include <cuda_runtime.h>
#include <cuda_bf16.h>
#include <cstdint>

#define NROWS 32768
#define CCLS  2048
#define DDIM  512

// ---- tensor-path tiling (round-7/11 proven config) ----
#define BM 128
#define BN 128
#define BK 64                    // bf16 elems per chunk (128B per row)
#define KCHUNKS 24               // 3 products x (512/64)
#define TILE_BYTES 16384         // 128 rows x 128B
#define STAGE_BYTES (2 * TILE_BYTES)
#define NSTAGES 3
#define SMEM_TOTAL  (NSTAGES * STAGE_BYTES)   // 98304

#define NRB (NROWS / BM)         // 256 rowblocks
#define GEMM_CTAS 296            // 2 CTAs/SM x 148 SMs, persistent
#define NEGHUGE -3.0e38f

// ---- scratch (__device__ globals; no cudaMalloc allowed) ----
__device__ __nv_bfloat16 g_Ah[(size_t)NROWS * DDIM];
__device__ __nv_bfloat16 g_Al[(size_t)NROWS * DDIM];
__device__ __nv_bfloat16 g_Bh[(size_t)CCLS * DDIM];   // compacted (visited only)
__device__ __nv_bfloat16 g_Bl[(size_t)CCLS * DDIM];   // compacted
__device__ float g_m2c[CCLS];                          // compacted ||mu||^2
__device__ int   g_pos[CCLS];                          // class -> compacted slot
__device__ int   g_V;                                  // number of visited classes

// ===========================================================================
// PTX helpers (all supported on plain sm_103 target)
// ===========================================================================
__device__ __forceinline__ uint32_t smem_u32(const void* p) {
    uint32_t a;
    asm("{ .reg .u64 t; cvta.to.shared.u64 t, %1; cvt.u32.u64 %0, t; }" : "=r"(a) : "l"(p));
    return a;
}

__device__ __forceinline__ void cp16(uint32_t dst, const void* src) {
    asm volatile("cp.async.cg.shared.global.L2::128B [%0], [%1], 16;" :: "r"(dst), "l"(src));
}
#define CP_COMMIT() asm volatile("cp.async.commit_group;" ::: "memory")
#define CP_WAIT1()  asm volatile("cp.async.wait_group 1;" ::: "memory")

__device__ __forceinline__ void ldsm4(uint32_t* r, uint32_t addr) {
    asm volatile("ldmatrix.sync.aligned.m8n8.x4.shared.b16 {%0,%1,%2,%3}, [%4];"
                 : "=r"(r[0]), "=r"(r[1]), "=r"(r[2]), "=r"(r[3]) : "r"(addr));
}

__device__ __forceinline__ void mma16816(float* d, const uint32_t* a, const uint32_t* b) {
    asm volatile("mma.sync.aligned.m16n8k16.row.col.f32.bf16.bf16.f32 "
                 "{%0,%1,%2,%3}, {%4,%5,%6,%7}, {%8,%9}, {%0,%1,%2,%3};"
                 : "+f"(d[0]), "+f"(d[1]), "+f"(d[2]), "+f"(d[3])
                 : "r"(a[0]), "r"(a[1]), "r"(a[2]), "r"(a[3]), "r"(b[0]), "r"(b[1]));
}

// ===========================================================================
// Kernel: prefix scan over visited flags -> pos / V
// ===========================================================================
__global__ __launch_bounds__(1024) void k_scan(const float* __restrict__ cK) {
    __shared__ int s[1024];
    const int t = threadIdx.x;
    const int f0 = (cK[2 * t]     != 0.f) ? 1 : 0;
    const int f1 = (cK[2 * t + 1] != 0.f) ? 1 : 0;
    const int p = f0 + f1;
    int v = p;
    s[t] = v;
    __syncthreads();
    #pragma unroll
    for (int off = 1; off < 1024; off <<= 1) {
        int add = (t >= off) ? s[t - off] : 0;
        __syncthreads();
        v += add;
        s[t] = v;
        __syncthreads();
    }
    const int excl = v - p;                  // exclusive prefix (pairs)
    g_pos[2 * t]     = excl;
    g_pos[2 * t + 1] = excl + f0;
    if (t == 1023) g_V = v;
}

// ===========================================================================
// Kernel: convert X -> bf16 hi/lo
// ===========================================================================
__global__ __launch_bounds__(256) void k_convX(const float* __restrict__ X) {
    const int idx = blockIdx.x * 256 + threadIdx.x;        // float4 index
    float4 v = ((const float4*)X)[idx];
    __nv_bfloat16 h0 = __float2bfloat16(v.x), h1 = __float2bfloat16(v.y);
    __nv_bfloat16 h2 = __float2bfloat16(v.z), h3 = __float2bfloat16(v.w);
    __nv_bfloat16 l0 = __float2bfloat16(v.x - __bfloat162float(h0));
    __nv_bfloat16 l1 = __float2bfloat16(v.y - __bfloat162float(h1));
    __nv_bfloat16 l2 = __float2bfloat16(v.z - __bfloat162float(h2));
    __nv_bfloat16 l3 = __float2bfloat16(v.w - __bfloat162float(h3));
    __nv_bfloat162* Ah = (__nv_bfloat162*)g_Ah;
    __nv_bfloat162* Al = (__nv_bfloat162*)g_Al;
    __nv_bfloat162 p;
    p.x = h0; p.y = h1; Ah[idx * 2]     = p;
    p.x = h2; p.y = h3; Ah[idx * 2 + 1] = p;
    p.x = l0; p.y = l1; Al[idx * 2]     = p;
    p.x = l2; p.y = l3; Al[idx * 2 + 1] = p;
}

// ===========================================================================
// Kernel: convert visited MU rows -> compacted bf16 hi/lo + m2
// ===========================================================================
__global__ __launch_bounds__(128) void k_convMU(const float* __restrict__ MU,
                                                const float* __restrict__ cK) {
    const int c = blockIdx.x;
    if (cK[c] == 0.f) return;                 // unvisited: skip entirely
    const int p = g_pos[c];
    const size_t src = (size_t)c * DDIM;
    const size_t dst = (size_t)p * DDIM;
    float s = 0.f;
    #pragma unroll
    for (int j = 0; j < 4; j++) {
        int d = threadIdx.x + j * 128;
        float x = MU[src + d];
        __nv_bfloat16 h = __float2bfloat16(x);
        __nv_bfloat16 l = __float2bfloat16(x - __bfloat162float(h));
        g_Bh[dst + d] = h;
        g_Bl[dst + d] = l;
        s = fmaf(x, x, s);
    }
    #pragma unroll
    for (int o = 16; o; o >>= 1) s += __shfl_xor_sync(0xffffffffu, s, o);
    __shared__ float sm[4];
    if ((threadIdx.x & 31) == 0) sm[threadIdx.x >> 5] = s;
    __syncthreads();
    if (threadIdx.x == 0) g_m2c[p] = sm[0] + sm[1] + sm[2] + sm[3];
}

// ===========================================================================
// Kernel: PERSISTENT HMMA GEMM over COMPACTED columns; compacted stores.
// S[i][p] = 2*(x_i . mu_{idx[p]}) - m2c[p],  p in [0, V)
// grid = 296 CTAs (2/SM), each loops over tiles -> no wave quantization.
// ===========================================================================
__device__ __forceinline__ void load_chunk(uint32_t stb, int t,
                                           int bm, int bn, int tid) {
    const int phase = t >> 3;
    const int koff  = (t & 7) * BK;
    const __nv_bfloat16* A = (phase == 1) ? g_Al : g_Ah;
    const __nv_bfloat16* B = (phase == 2) ? g_Bl : g_Bh;
    const uint32_t bs = stb + TILE_BYTES;
    #pragma unroll
    for (int i = 0; i < 4; i++) {
        int q = tid + i * 256;
        int r = q >> 3, c = q & 7;
        uint32_t off = r * 128 + ((c * 16) ^ ((r & 7) << 4));
        cp16(stb + off, A + (size_t)(bm + r) * DDIM + koff + c * 8);
    }
    #pragma unroll
    for (int i = 0; i < 4; i++) {
        int q = tid + i * 256;
        int r = q >> 3, c = q & 7;
        uint32_t off = r * 128 + ((c * 16) ^ ((r & 7) << 4));
        cp16(bs + off, B + (size_t)(bn + r) * DDIM + koff + c * 8);
    }
}

__global__ __launch_bounds__(256, 2) void k_gemm_mma(float* __restrict__ S) {
    extern __shared__ char smem[];
    const uint32_t sb = smem_u32(smem);
    const int tid = threadIdx.x;
    const int wid = tid >> 5, l = tid & 31;
    const int wm = (wid & 1) * 64;
    const int wn = (wid >> 1) * 32;

    const int V = g_V;
    const int nct = (V + BN - 1) / BN;        // active col tiles (runtime)
    const int ntiles = nct * NRB;

    // per-lane ldmatrix addressing (swizzle nibble depends only on lane)
    const uint32_t sw   = (uint32_t)(l & 7) << 4;
    const int rowA = wm + (l & 15);
    const uint32_t aColSel = ((uint32_t)(l >> 4)) << 4;
    const int rowB = wn + ((l >> 4) << 3) + (l & 7);
    const uint32_t bColSel = ((uint32_t)((l >> 3) & 1)) << 4;

    for (int tile = blockIdx.x; tile < ntiles; tile += GEMM_CTAS) {
        const int rb = tile / nct;
        const int ct = tile - rb * nct;
        const int bm = rb * BM;
        const int bn = ct * BN;

        float acc[4][4][4];
        #pragma unroll
        for (int i = 0; i < 4; i++)
            #pragma unroll
            for (int j = 0; j < 4; j++)
                #pragma unroll
                for (int k = 0; k < 4; k++) acc[i][j][k] = 0.f;

        load_chunk(sb + 0 * STAGE_BYTES, 0, bm, bn, tid); CP_COMMIT();
        load_chunk(sb + 1 * STAGE_BYTES, 1, bm, bn, tid); CP_COMMIT();

        int rs = 0, ws = 2;
        for (int t = 0; t < KCHUNKS; t++) {
            CP_WAIT1();
            __syncthreads();

            if (t + 2 < KCHUNKS) load_chunk(sb + ws * STAGE_BYTES, t + 2, bm, bn, tid);
            CP_COMMIT();

            const uint32_t as = sb + rs * STAGE_BYTES;
            const uint32_t bsm = as + TILE_BYTES;

            #pragma unroll
            for (int ks = 0; ks < 4; ks++) {
                const uint32_t kb = (uint32_t)ks * 32;
                uint32_t a[4][4], b[2][4];
                #pragma unroll
                for (int bt = 0; bt < 2; bt++)
                    ldsm4(b[bt], bsm + (uint32_t)(rowB + bt * 16) * 128 + ((kb + bColSel) ^ sw));
                #pragma unroll
                for (int mt = 0; mt < 4; mt++)
                    ldsm4(a[mt], as + (uint32_t)(rowA + mt * 16) * 128 + ((kb + aColSel) ^ sw));
                #pragma unroll
                for (int mt = 0; mt < 4; mt++) {
                    mma16816(acc[mt][0], a[mt], &b[0][0]);
                    mma16816(acc[mt][1], a[mt], &b[0][2]);
                    mma16816(acc[mt][2], a[mt], &b[1][0]);
                    mma16816(acc[mt][3], a[mt], &b[1][2]);
                }
            }

            rs = (rs == 2) ? 0 : rs + 1;
            ws = (ws == 2) ? 0 : ws + 1;
        }

        // epilogue: coalesced stores at COMPACTED columns, guard c < V
        const int ccomp = bn + wn + (l & 3) * 2;
        const int rbase = bm + wm + (l >> 2);
        float m2v[4][2];
        bool  ok0[4], ok1[4];
        #pragma unroll
        for (int nt = 0; nt < 4; nt++) {
            const int c0 = ccomp + nt * 8;
            ok0[nt] = (c0 < V); ok1[nt] = (c0 + 1 < V);
            m2v[nt][0] = ok0[nt] ? g_m2c[c0]     : 0.f;
            m2v[nt][1] = ok1[nt] ? g_m2c[c0 + 1] : 0.f;
        }
        #pragma unroll
        for (int mt = 0; mt < 4; mt++) {
            const int r0 = rbase + mt * 16;
            const int r1 = r0 + 8;
            #pragma unroll
            for (int nt = 0; nt < 4; nt++) {
                const int c0 = ccomp + nt * 8;
                if (ok1[nt]) {
                    float2 v0, v1;
                    v0.x = 2.f * acc[mt][nt][0] - m2v[nt][0];
                    v0.y = 2.f * acc[mt][nt][1] - m2v[nt][1];
                    v1.x = 2.f * acc[mt][nt][2] - m2v[nt][0];
                    v1.y = 2.f * acc[mt][nt][3] - m2v[nt][1];
                    *(float2*)(S + (size_t)r0 * CCLS + c0) = v0;
                    *(float2*)(S + (size_t)r1 * CCLS + c0) = v1;
                } else if (ok0[nt]) {
                    S[(size_t)r0 * CCLS + c0] = 2.f * acc[mt][nt][0] - m2v[nt][0];
                    S[(size_t)r1 * CCLS + c0] = 2.f * acc[mt][nt][2] - m2v[nt][0];
                }
            }
        }
    }
}

// ===========================================================================
// Kernel: per-row softmax on compacted scores + gather-expand to full row.
// Pad-region loads are skipped (not just masked) to cut DRAM read traffic.
// Unvisited classes output exactly 0 (reference underflows to 0 in fp32).
// ===========================================================================
__device__ __forceinline__ float block_red(float v, int mode, float* sred, int tid) {
    #pragma unroll
    for (int o = 16; o; o >>= 1) {
        float t = __shfl_xor_sync(0xffffffffu, v, o);
        v = (mode == 1) ? fmaxf(v, t) : (v + t);
    }
    __syncthreads();
    if ((tid & 31) == 0) sred[tid >> 5] = v;
    __syncthreads();
    float r;
    if (mode == 1) {
        r = fmaxf(fmaxf(fmaxf(sred[0], sred[1]), fmaxf(sred[2], sred[3])),
                  fmaxf(fmaxf(sred[4], sred[5]), fmaxf(sred[6], sred[7])));
    } else {
        r = ((sred[0] + sred[1]) + (sred[2] + sred[3])) +
            ((sred[4] + sred[5]) + (sred[6] + sred[7]));
    }
    return r;
}

__global__ __launch_bounds__(256) void k_softmax(float* __restrict__ S,
                                                 const float* __restrict__ cK) {
    __shared__ float sm_e[CCLS];
    __shared__ float sred[8];
    const int row = blockIdx.x;
    const int tid = threadIdx.x;
    const int V = g_V;
    float* srow = S + (size_t)row * CCLS;
    float4* sp = (float4*)srow;

    // load compacted scores; SKIP loads in pad region (p >= V)
    const int p0 = tid * 4;
    const int p1 = 1024 + tid * 4;
    float4 v0 = make_float4(NEGHUGE, NEGHUGE, NEGHUGE, NEGHUGE);
    float4 v1 = make_float4(NEGHUGE, NEGHUGE, NEGHUGE, NEGHUGE);
    if (p0 + 3 < V) {
        v0 = sp[tid];
    } else if (p0 < V) {
        v0.x = srow[p0];
        if (p0 + 1 < V) v0.y = srow[p0 + 1];
        if (p0 + 2 < V) v0.z = srow[p0 + 2];
    }
    if (p1 + 3 < V) {
        v1 = sp[tid + 256];
    } else if (p1 < V) {
        v1.x = srow[p1];
        if (p1 + 1 < V) v1.y = srow[p1 + 1];
        if (p1 + 2 < V) v1.z = srow[p1 + 2];
    }

    float mx = fmaxf(fmaxf(fmaxf(v0.x, v0.y), fmaxf(v0.z, v0.w)),
                     fmaxf(fmaxf(v1.x, v1.y), fmaxf(v1.z, v1.w)));
    mx = block_red(mx, 1, sred, tid);

    float4 e0, e1;
    e0.x = __expf(v0.x - mx); e0.y = __expf(v0.y - mx);
    e0.z = __expf(v0.z - mx); e0.w = __expf(v0.w - mx);
    e1.x = __expf(v1.x - mx); e1.y = __expf(v1.y - mx);
    e1.z = __expf(v1.z - mx); e1.w = __expf(v1.w - mx);
    float sum = ((e0.x + e0.y) + (e0.z + e0.w)) + ((e1.x + e1.y) + (e1.z + e1.w));
    sum = block_red(sum, 2, sred, tid);
    const float inv = 1.f / sum;

    // stage normalized probs in smem (compacted index space)
    ((float4*)sm_e)[tid]       = make_float4(e0.x * inv, e0.y * inv, e0.z * inv, e0.w * inv);
    ((float4*)sm_e)[tid + 256] = make_float4(e1.x * inv, e1.y * inv, e1.z * inv, e1.w * inv);
    __syncthreads();

    // gather-expand to full column space, coalesced float4 stores
    const float4* cp = (const float4*)cK;
    const int4*   qp = (const int4*)g_pos;
    float4 c0 = cp[tid], c1 = cp[tid + 256];
    int4   q0 = qp[tid], q1 = qp[tid + 256];
    float4 o0, o1;
    o0.x = (c0.x == 0.f) ? 0.f : sm_e[q0.x];
    o0.y = (c0.y == 0.f) ? 0.f : sm_e[q0.y];
    o0.z = (c0.z == 0.f) ? 0.f : sm_e[q0.z];
    o0.w = (c0.w == 0.f) ? 0.f : sm_e[q0.w];
    o1.x = (c1.x == 0.f) ? 0.f : sm_e[q1.x];
    o1.y = (c1.y == 0.f) ? 0.f : sm_e[q1.y];
    o1.z = (c1.z == 0.f) ? 0.f : sm_e[q1.z];
    o1.w = (c1.w == 0.f) ? 0.f : sm_e[q1.w];
    sp[tid]       = o0;
    sp[tid + 256] = o1;
}

// ===========================================================================
extern "C" void kernel_launch(void* const* d_in, const int* in_sizes, int n_in,
                              void* d_out, int out_size) {
    const float* X  = (const float*)d_in[0];   // (N, D) fp32
    const float* MU = (const float*)d_in[1];   // (C, D) fp32
    const float* cK = (const float*)d_in[2];   // (C,)   fp32
    float* out = (float*)d_out;                // (N, C) fp32

    cudaFuncSetAttribute(k_gemm_mma, cudaFuncAttributeMaxDynamicSharedMemorySize, SMEM_TOTAL);

    k_scan<<<1, 1024>>>(cK);
    k_convX<<<(NROWS * DDIM) / 4 / 256, 256>>>(X);
    k_convMU<<<CCLS, 128>>>(MU, cK);

    k_gemm_mma<<<GEMM_CTAS, 256, SMEM_TOTAL>>>(out);

    k_softmax<<<NROWS, 256>>>(out, cK);
}

// round 15
// speedup vs baseline: 1.4373x; 1.0392x over previous
#include <cuda_runtime.h>
#include <cuda_bf16.h>
#include <cstdint>

#define NROWS 32768
#define CCLS  2048
#define DDIM  512

// ---- tensor-path tiling (round-7/11 proven config) ----
#define BM 128
#define BN 128
#define BK 64                    // bf16 elems per chunk (128B per row)
#define KCHUNKS 24               // 3 products x (512/64)
#define TILE_BYTES 16384         // 128 rows x 128B
#define STAGE_BYTES (2 * TILE_BYTES)
#define NSTAGES 3
#define SMEM_TOTAL  (NSTAGES * STAGE_BYTES)   // 98304

#define NEGHUGE -3.0e38f

// ---- scratch (__device__ globals; no cudaMalloc allowed) ----
__device__ __nv_bfloat16 g_Ah[(size_t)NROWS * DDIM];
__device__ __nv_bfloat16 g_Al[(size_t)NROWS * DDIM];
__device__ __nv_bfloat16 g_Bh[(size_t)CCLS * DDIM];   // compacted (visited only)
__device__ __nv_bfloat16 g_Bl[(size_t)CCLS * DDIM];   // compacted
__device__ float g_m2c[CCLS];                          // compacted ||mu||^2
__device__ int   g_pos[CCLS];                          // class -> compacted slot
__device__ int   g_V;                                  // number of visited classes

// ===========================================================================
// PTX helpers (all supported on plain sm_103 target)
// ===========================================================================
__device__ __forceinline__ uint32_t smem_u32(const void* p) {
    uint32_t a;
    asm("{ .reg .u64 t; cvta.to.shared.u64 t, %1; cvt.u32.u64 %0, t; }" : "=r"(a) : "l"(p));
    return a;
}

__device__ __forceinline__ void cp16(uint32_t dst, const void* src) {
    asm volatile("cp.async.cg.shared.global.L2::128B [%0], [%1], 16;" :: "r"(dst), "l"(src));
}
#define CP_COMMIT() asm volatile("cp.async.commit_group;" ::: "memory")
#define CP_WAIT1()  asm volatile("cp.async.wait_group 1;" ::: "memory")

__device__ __forceinline__ void ldsm4(uint32_t* r, uint32_t addr) {
    asm volatile("ldmatrix.sync.aligned.m8n8.x4.shared.b16 {%0,%1,%2,%3}, [%4];"
                 : "=r"(r[0]), "=r"(r[1]), "=r"(r[2]), "=r"(r[3]) : "r"(addr));
}

__device__ __forceinline__ void mma16816(float* d, const uint32_t* a, const uint32_t* b) {
    asm volatile("mma.sync.aligned.m16n8k16.row.col.f32.bf16.bf16.f32 "
                 "{%0,%1,%2,%3}, {%4,%5,%6,%7}, {%8,%9}, {%0,%1,%2,%3};"
                 : "+f"(d[0]), "+f"(d[1]), "+f"(d[2]), "+f"(d[3])
                 : "r"(a[0]), "r"(a[1]), "r"(a[2]), "r"(a[3]), "r"(b[0]), "r"(b[1]));
}

// ===========================================================================
// Kernel: prefix scan over visited flags -> pos / V
// ===========================================================================
__global__ __launch_bounds__(1024) void k_scan(const float* __restrict__ cK) {
    __shared__ int s[1024];
    const int t = threadIdx.x;
    const int f0 = (cK[2 * t]     != 0.f) ? 1 : 0;
    const int f1 = (cK[2 * t + 1] != 0.f) ? 1 : 0;
    const int p = f0 + f1;
    int v = p;
    s[t] = v;
    __syncthreads();
    #pragma unroll
    for (int off = 1; off < 1024; off <<= 1) {
        int add = (t >= off) ? s[t - off] : 0;
        __syncthreads();
        v += add;
        s[t] = v;
        __syncthreads();
    }
    const int excl = v - p;                  // exclusive prefix (pairs)
    g_pos[2 * t]     = excl;
    g_pos[2 * t + 1] = excl + f0;
    if (t == 1023) g_V = v;
}

// ===========================================================================
// Kernel: convert X -> bf16 hi/lo
// ===========================================================================
__global__ __launch_bounds__(256) void k_convX(const float* __restrict__ X) {
    const int idx = blockIdx.x * 256 + threadIdx.x;        // float4 index
    float4 v = ((const float4*)X)[idx];
    __nv_bfloat16 h0 = __float2bfloat16(v.x), h1 = __float2bfloat16(v.y);
    __nv_bfloat16 h2 = __float2bfloat16(v.z), h3 = __float2bfloat16(v.w);
    __nv_bfloat16 l0 = __float2bfloat16(v.x - __bfloat162float(h0));
    __nv_bfloat16 l1 = __float2bfloat16(v.y - __bfloat162float(h1));
    __nv_bfloat16 l2 = __float2bfloat16(v.z - __bfloat162float(h2));
    __nv_bfloat16 l3 = __float2bfloat16(v.w - __bfloat162float(h3));
    __nv_bfloat162* Ah = (__nv_bfloat162*)g_Ah;
    __nv_bfloat162* Al = (__nv_bfloat162*)g_Al;
    __nv_bfloat162 p;
    p.x = h0; p.y = h1; Ah[idx * 2]     = p;
    p.x = h2; p.y = h3; Ah[idx * 2 + 1] = p;
    p.x = l0; p.y = l1; Al[idx * 2]     = p;
    p.x = l2; p.y = l3; Al[idx * 2 + 1] = p;
}

// ===========================================================================
// Kernel: convert visited MU rows -> compacted bf16 hi/lo + m2
// ===========================================================================
__global__ __launch_bounds__(128) void k_convMU(const float* __restrict__ MU,
                                                const float* __restrict__ cK) {
    const int c = blockIdx.x;
    if (cK[c] == 0.f) return;                 // unvisited: skip entirely
    const int p = g_pos[c];
    const size_t src = (size_t)c * DDIM;
    const size_t dst = (size_t)p * DDIM;
    float s = 0.f;
    #pragma unroll
    for (int j = 0; j < 4; j++) {
        int d = threadIdx.x + j * 128;
        float x = MU[src + d];
        __nv_bfloat16 h = __float2bfloat16(x);
        __nv_bfloat16 l = __float2bfloat16(x - __bfloat162float(h));
        g_Bh[dst + d] = h;
        g_Bl[dst + d] = l;
        s = fmaf(x, x, s);
    }
    #pragma unroll
    for (int o = 16; o; o >>= 1) s += __shfl_xor_sync(0xffffffffu, s, o);
    __shared__ float sm[4];
    if ((threadIdx.x & 31) == 0) sm[threadIdx.x >> 5] = s;
    __syncthreads();
    if (threadIdx.x == 0) g_m2c[p] = sm[0] + sm[1] + sm[2] + sm[3];
}

// ===========================================================================
// Kernel: HMMA GEMM over COMPACTED columns (round-11 exact: non-persistent,
// grid (16,256), dead tiles exit early). Compacted coalesced stores.
// S[i][p] = 2*(x_i . mu_{idx[p]}) - m2c[p],  p in [0, V)
// ===========================================================================
__device__ __forceinline__ void load_chunk(uint32_t stb, int t,
                                           int bm, int bn, int tid) {
    const int phase = t >> 3;
    const int koff  = (t & 7) * BK;
    const __nv_bfloat16* A = (phase == 1) ? g_Al : g_Ah;
    const __nv_bfloat16* B = (phase == 2) ? g_Bl : g_Bh;
    const uint32_t bs = stb + TILE_BYTES;
    #pragma unroll
    for (int i = 0; i < 4; i++) {
        int q = tid + i * 256;
        int r = q >> 3, c = q & 7;
        uint32_t off = r * 128 + ((c * 16) ^ ((r & 7) << 4));
        cp16(stb + off, A + (size_t)(bm + r) * DDIM + koff + c * 8);
    }
    #pragma unroll
    for (int i = 0; i < 4; i++) {
        int q = tid + i * 256;
        int r = q >> 3, c = q & 7;
        uint32_t off = r * 128 + ((c * 16) ^ ((r & 7) << 4));
        cp16(bs + off, B + (size_t)(bn + r) * DDIM + koff + c * 8);
    }
}

__global__ __launch_bounds__(256, 2) void k_gemm_mma(float* __restrict__ S) {
    const int bn = blockIdx.x * BN;
    const int V = g_V;
    if (bn >= V) return;                      // tile fully in pad region

    extern __shared__ char smem[];
    const uint32_t sb = smem_u32(smem);
    const int tid = threadIdx.x;
    const int wid = tid >> 5, l = tid & 31;
    const int bm = blockIdx.y * BM;
    const int wm = (wid & 1) * 64;
    const int wn = (wid >> 1) * 32;

    float acc[4][4][4];
    #pragma unroll
    for (int i = 0; i < 4; i++)
        #pragma unroll
        for (int j = 0; j < 4; j++)
            #pragma unroll
            for (int k = 0; k < 4; k++) acc[i][j][k] = 0.f;

    const uint32_t sw   = (uint32_t)(l & 7) << 4;
    const int rowA = wm + (l & 15);
    const uint32_t aColSel = ((uint32_t)(l >> 4)) << 4;
    const int rowB = wn + ((l >> 4) << 3) + (l & 7);
    const uint32_t bColSel = ((uint32_t)((l >> 3) & 1)) << 4;

    load_chunk(sb + 0 * STAGE_BYTES, 0, bm, bn, tid); CP_COMMIT();
    load_chunk(sb + 1 * STAGE_BYTES, 1, bm, bn, tid); CP_COMMIT();

    int rs = 0, ws = 2;
    for (int t = 0; t < KCHUNKS; t++) {
        CP_WAIT1();
        __syncthreads();

        if (t + 2 < KCHUNKS) load_chunk(sb + ws * STAGE_BYTES, t + 2, bm, bn, tid);
        CP_COMMIT();

        const uint32_t as = sb + rs * STAGE_BYTES;
        const uint32_t bs = as + TILE_BYTES;

        #pragma unroll
        for (int ks = 0; ks < 4; ks++) {
            const uint32_t kb = (uint32_t)ks * 32;
            uint32_t a[4][4], b[2][4];
            #pragma unroll
            for (int bt = 0; bt < 2; bt++)
                ldsm4(b[bt], bs + (uint32_t)(rowB + bt * 16) * 128 + ((kb + bColSel) ^ sw));
            #pragma unroll
            for (int mt = 0; mt < 4; mt++)
                ldsm4(a[mt], as + (uint32_t)(rowA + mt * 16) * 128 + ((kb + aColSel) ^ sw));
            #pragma unroll
            for (int mt = 0; mt < 4; mt++) {
                mma16816(acc[mt][0], a[mt], &b[0][0]);
                mma16816(acc[mt][1], a[mt], &b[0][2]);
                mma16816(acc[mt][2], a[mt], &b[1][0]);
                mma16816(acc[mt][3], a[mt], &b[1][2]);
            }
        }

        rs = (rs == 2) ? 0 : rs + 1;
        ws = (ws == 2) ? 0 : ws + 1;
    }

    // epilogue: coalesced stores at COMPACTED columns, guard c < V
    const int ccomp = bn + wn + (l & 3) * 2;
    const int rbase = bm + wm + (l >> 2);
    float m2v[4][2];
    bool  ok0[4], ok1[4];
    #pragma unroll
    for (int nt = 0; nt < 4; nt++) {
        const int c0 = ccomp + nt * 8;
        ok0[nt] = (c0 < V); ok1[nt] = (c0 + 1 < V);
        m2v[nt][0] = ok0[nt] ? g_m2c[c0]     : 0.f;
        m2v[nt][1] = ok1[nt] ? g_m2c[c0 + 1] : 0.f;
    }
    #pragma unroll
    for (int mt = 0; mt < 4; mt++) {
        const int r0 = rbase + mt * 16;
        const int r1 = r0 + 8;
        #pragma unroll
        for (int nt = 0; nt < 4; nt++) {
            const int c0 = ccomp + nt * 8;
            if (ok1[nt]) {
                float2 v0, v1;
                v0.x = 2.f * acc[mt][nt][0] - m2v[nt][0];
                v0.y = 2.f * acc[mt][nt][1] - m2v[nt][1];
                v1.x = 2.f * acc[mt][nt][2] - m2v[nt][0];
                v1.y = 2.f * acc[mt][nt][3] - m2v[nt][1];
                *(float2*)(S + (size_t)r0 * CCLS + c0) = v0;
                *(float2*)(S + (size_t)r1 * CCLS + c0) = v1;
            } else if (ok0[nt]) {
                S[(size_t)r0 * CCLS + c0] = 2.f * acc[mt][nt][0] - m2v[nt][0];
                S[(size_t)r1 * CCLS + c0] = 2.f * acc[mt][nt][2] - m2v[nt][0];
            }
        }
    }
}

// ===========================================================================
// Kernel: per-row softmax on compacted scores + gather-expand to full row.
// Pad-region loads are skipped (not just masked) to cut DRAM read traffic.
// Unvisited classes output exactly 0 (reference underflows to 0 in fp32).
// ===========================================================================
__device__ __forceinline__ float block_red(float v, int mode, float* sred, int tid) {
    #pragma unroll
    for (int o = 16; o; o >>= 1) {
        float t = __shfl_xor_sync(0xffffffffu, v, o);
        v = (mode == 1) ? fmaxf(v, t) : (v + t);
    }
    __syncthreads();
    if ((tid & 31) == 0) sred[tid >> 5] = v;
    __syncthreads();
    float r;
    if (mode == 1) {
        r = fmaxf(fmaxf(fmaxf(sred[0], sred[1]), fmaxf(sred[2], sred[3])),
                  fmaxf(fmaxf(sred[4], sred[5]), fmaxf(sred[6], sred[7])));
    } else {
        r = ((sred[0] + sred[1]) + (sred[2] + sred[3])) +
            ((sred[4] + sred[5]) + (sred[6] + sred[7]));
    }
    return r;
}

__global__ __launch_bounds__(256) void k_softmax(float* __restrict__ S,
                                                 const float* __restrict__ cK) {
    __shared__ float sm_e[CCLS];
    __shared__ float sred[8];
    const int row = blockIdx.x;
    const int tid = threadIdx.x;
    const int V = g_V;
    float* srow = S + (size_t)row * CCLS;
    float4* sp = (float4*)srow;

    // load compacted scores; SKIP loads in pad region (p >= V)
    const int p0 = tid * 4;
    const int p1 = 1024 + tid * 4;
    float4 v0 = make_float4(NEGHUGE, NEGHUGE, NEGHUGE, NEGHUGE);
    float4 v1 = make_float4(NEGHUGE, NEGHUGE, NEGHUGE, NEGHUGE);
    if (p0 + 3 < V) {
        v0 = sp[tid];
    } else if (p0 < V) {
        v0.x = srow[p0];
        if (p0 + 1 < V) v0.y = srow[p0 + 1];
        if (p0 + 2 < V) v0.z = srow[p0 + 2];
    }
    if (p1 + 3 < V) {
        v1 = sp[tid + 256];
    } else if (p1 < V) {
        v1.x = srow[p1];
        if (p1 + 1 < V) v1.y = srow[p1 + 1];
        if (p1 + 2 < V) v1.z = srow[p1 + 2];
    }

    float mx = fmaxf(fmaxf(fmaxf(v0.x, v0.y), fmaxf(v0.z, v0.w)),
                     fmaxf(fmaxf(v1.x, v1.y), fmaxf(v1.z, v1.w)));
    mx = block_red(mx, 1, sred, tid);

    float4 e0, e1;
    e0.x = __expf(v0.x - mx); e0.y = __expf(v0.y - mx);
    e0.z = __expf(v0.z - mx); e0.w = __expf(v0.w - mx);
    e1.x = __expf(v1.x - mx); e1.y = __expf(v1.y - mx);
    e1.z = __expf(v1.z - mx); e1.w = __expf(v1.w - mx);
    float sum = ((e0.x + e0.y) + (e0.z + e0.w)) + ((e1.x + e1.y) + (e1.z + e1.w));
    sum = block_red(sum, 2, sred, tid);
    const float inv = 1.f / sum;

    // stage normalized probs in smem (compacted index space)
    ((float4*)sm_e)[tid]       = make_float4(e0.x * inv, e0.y * inv, e0.z * inv, e0.w * inv);
    ((float4*)sm_e)[tid + 256] = make_float4(e1.x * inv, e1.y * inv, e1.z * inv, e1.w * inv);
    __syncthreads();

    // gather-expand to full column space, coalesced float4 stores
    const float4* cp = (const float4*)cK;
    const int4*   qp = (const int4*)g_pos;
    float4 c0 = cp[tid], c1 = cp[tid + 256];
    int4   q0 = qp[tid], q1 = qp[tid + 256];
    float4 o0, o1;
    o0.x = (c0.x == 0.f) ? 0.f : sm_e[q0.x];
    o0.y = (c0.y == 0.f) ? 0.f : sm_e[q0.y];
    o0.z = (c0.z == 0.f) ? 0.f : sm_e[q0.z];
    o0.w = (c0.w == 0.f) ? 0.f : sm_e[q0.w];
    o1.x = (c1.x == 0.f) ? 0.f : sm_e[q1.x];
    o1.y = (c1.y == 0.f) ? 0.f : sm_e[q1.y];
    o1.z = (c1.z == 0.f) ? 0.f : sm_e[q1.z];
    o1.w = (c1.w == 0.f) ? 0.f : sm_e[q1.w];
    sp[tid]       = o0;
    sp[tid + 256] = o1;
}

// ===========================================================================
extern "C" void kernel_launch(void* const* d_in, const int* in_sizes, int n_in,
                              void* d_out, int out_size) {
    const float* X  = (const float*)d_in[0];   // (N, D) fp32
    const float* MU = (const float*)d_in[1];   // (C, D) fp32
    const float* cK = (const float*)d_in[2];   // (C,)   fp32
    float* out = (float*)d_out;                // (N, C) fp32

    cudaFuncSetAttribute(k_gemm_mma, cudaFuncAttributeMaxDynamicSharedMemorySize, SMEM_TOTAL);

    k_scan<<<1, 1024>>>(cK);
    k_convX<<<(NROWS * DDIM) / 4 / 256, 256>>>(X);
    k_convMU<<<CCLS, 128>>>(MU, cK);

    dim3 grid(CCLS / BN, NROWS / BM);          // (16, 256); dead tiles exit early
    k_gemm_mma<<<grid, 256, SMEM_TOTAL>>>(out);

    k_softmax<<<NROWS, 256>>>(out, cK);
}